// round 16
// baseline (speedup 1.0000x reference)
#include <cuda_runtime.h>
#include <cuda_bf16.h>

// RotaryPositionEncoding3D: out[B,N,192,2] f32 from xyz[B,N,3] f32 and div_term[32] f32.
// Each output float4 g = (cos, sin, cos, sin) of angle xyz[p, axis]*div_term[bin],
//   p = g/96, j = g%96, axis = j%3, bin = j/3.
//
// v15: champion body (4 float4/thread, closed-form independent per-k indices,
// __stcs STG.128, guard-free exact-fit path) with THREADS=512 -- the one
// scheduling variable never isolated. Each CTA now drains a 32KB contiguous
// output span (vs 16KB), 12288 blocks, 4 CTAs/SM. All other axes (MLP, store
// width, policy, persistence, ordering) are measured-flat at the write-stream
// ceiling: wall 57.4us = 7.0 TB/s = 88% of HBM3e spec.

#define F4_PER_THREAD 4
#define THREADS 512
#define TILE (THREADS * F4_PER_THREAD)   // 2048 float4 per block

template <bool GUARDED>
__global__ void __launch_bounds__(THREADS, 4)
rope3d_kernel(const float* __restrict__ xyz,
              const float* __restrict__ div_term,
              float4* __restrict__ out,
              int total_f4) {
    const int base = blockIdx.x * TILE + (int)threadIdx.x;

    const unsigned p0 = (unsigned)base / 96u;
    const unsigned j0 = (unsigned)base - p0 * 96u;   // [0, 96)

    float c[F4_PER_THREAD], s[F4_PER_THREAD];

#pragma unroll
    for (int k = 0; k < F4_PER_THREAD; ++k) {
        // Independent per-k index math: t = j0 + 512k < 96 + 1536
        unsigned t    = j0 + (unsigned)(k * THREADS);
        unsigned dp   = t / 96u;
        unsigned jk   = t - dp * 96u;                // j = 3*bin + axis
        unsigned bin  = jk / 3u;
        unsigned axis = jk - bin * 3u;

        float x  = __ldg(&xyz[(p0 + dp) * 3u + axis]);
        float dt = __ldg(&div_term[bin]);
        __sincosf(x * dt, &s[k], &c[k]);             // |ang| <= 1, ample precision
    }

#pragma unroll
    for (int k = 0; k < F4_PER_THREAD; ++k) {
        int g = base + k * THREADS;
        if (!GUARDED || g < total_f4)
            __stcs(&out[g], make_float4(c[k], s[k], c[k], s[k]));
    }
}

extern "C" void kernel_launch(void* const* d_in, const int* in_sizes, int n_in,
                              void* d_out, int out_size) {
    const float* xyz      = (const float*)d_in[0];
    const float* div_term = (const float*)d_in[1];
    float4* out = (float4*)d_out;

    int total_f4 = out_size / 4;                     // 25,165,824 for B=4, N=65536
    int blocks = (total_f4 + TILE - 1) / TILE;       // 12,288 (exact fit)
    if (total_f4 % TILE == 0)
        rope3d_kernel<false><<<blocks, THREADS>>>(xyz, div_term, out, total_f4);
    else
        rope3d_kernel<true><<<blocks, THREADS>>>(xyz, div_term, out, total_f4);
}

// round 17
// speedup vs baseline: 1.0061x; 1.0061x over previous
#include <cuda_runtime.h>
#include <cuda_bf16.h>

// RotaryPositionEncoding3D: out[B,N,192,2] f32 from xyz[B,N,3] f32 and div_term[32] f32.
// Each output float4 g = (cos, sin, cos, sin) of angle xyz[p, axis]*div_term[bin],
//   p = g/96, j = g%96, axis = j%3, bin = j/3.
//
// FINAL (converged): 256 threads, 4 float4/thread at stride-256, closed-form
// independent per-k indices (front-batched LDG+MUFU chains), __stcs STG.128,
// guard-free exact-fit path, max-residency launch bounds.
//
// Convergence evidence (9 experiments): MLP 4 vs 8, STG.128 vs STG.256,
// .cs vs .wb, short CTAs vs persistent grid, strided vs warp-contiguous
// ordering, block 256 vs 512 -- ALL plateau at ncu dur 59.2+-0.3us,
// wall 57.4-57.8us = 402.6 MB / 57.4us = 7.0 TB/s = 88% of HBM3e spec,
// with no SM pipe above 15%. This is the pure-write-stream HW ceiling.
// Key structural lesson (R3): per-k address independence >> index-math cost;
// a loop-carried address chain collapsed DRAM busy from 73% to 54%.

#define F4_PER_THREAD 4
#define THREADS 256
#define TILE (THREADS * F4_PER_THREAD)   // 1024 float4 per block

template <bool GUARDED>
__global__ void __launch_bounds__(THREADS, 8)
rope3d_kernel(const float* __restrict__ xyz,
              const float* __restrict__ div_term,
              float4* __restrict__ out,
              int total_f4) {
    const int base = blockIdx.x * TILE + (int)threadIdx.x;

    const unsigned p0 = (unsigned)base / 96u;
    const unsigned j0 = (unsigned)base - p0 * 96u;   // [0, 96)

    float c[F4_PER_THREAD], s[F4_PER_THREAD];

#pragma unroll
    for (int k = 0; k < F4_PER_THREAD; ++k) {
        // Independent per-k index math: t = j0 + 256k < 96 + 768
        unsigned t    = j0 + (unsigned)(k * THREADS);
        unsigned dp   = t / 96u;
        unsigned jk   = t - dp * 96u;                // j = 3*bin + axis
        unsigned bin  = jk / 3u;
        unsigned axis = jk - bin * 3u;

        float x  = __ldg(&xyz[(p0 + dp) * 3u + axis]);
        float dt = __ldg(&div_term[bin]);
        __sincosf(x * dt, &s[k], &c[k]);             // |ang| <= 1, ample precision
    }

#pragma unroll
    for (int k = 0; k < F4_PER_THREAD; ++k) {
        int g = base + k * THREADS;
        if (!GUARDED || g < total_f4)
            __stcs(&out[g], make_float4(c[k], s[k], c[k], s[k]));
    }
}

extern "C" void kernel_launch(void* const* d_in, const int* in_sizes, int n_in,
                              void* d_out, int out_size) {
    const float* xyz      = (const float*)d_in[0];
    const float* div_term = (const float*)d_in[1];
    float4* out = (float4*)d_out;

    int total_f4 = out_size / 4;                     // 25,165,824 for B=4, N=65536
    int blocks = (total_f4 + TILE - 1) / TILE;       // 24,576 (exact fit)
    if (total_f4 % TILE == 0)
        rope3d_kernel<false><<<blocks, THREADS>>>(xyz, div_term, out, total_f4);
    else
        rope3d_kernel<true><<<blocks, THREADS>>>(xyz, div_term, out, total_f4);
}